// round 5
// baseline (speedup 1.0000x reference)
#include <cuda_runtime.h>

#define N_NODES 100000
#define N_EDGES 1000000
#define PAD 64   // max stored degree; deg~Poisson(10), P(>64) ~ 0

// ---------------- device scratch (no allocations allowed) ----------------
__device__ int   g_is64;
__device__ int   g_deg[N_NODES];
__device__ int   g_colpad[N_NODES * PAD];
__device__ float g_z[N_NODES * 64];   // x @ Wl1^T
__device__ float g_y[N_NODES * 64];   // x @ Wr1^T
__device__ float g_p[N_NODES * 2];    // h @ Wl2^T  (to be mean-aggregated)
__device__ float g_q[N_NODES * 2];    // h @ Wr2^T + b2 (local term)

// ---------------- init: zero degrees + dtype sniff ----------------
__global__ void k_init(const int* __restrict__ ei32) {
    int i = blockIdx.x * blockDim.x + threadIdx.x;
    if (i < N_NODES / 4) ((int4*)g_deg)[i] = make_int4(0, 0, 0, 0);
    if (i == 0) {
        // int64 nonneg < 2^31 => every odd int32 word is 0
        int any = 0;
        for (int s = 1; s < 64; s += 2) any |= ei32[s];
        g_is64 = (any == 0) ? 1 : 0;
    }
}

// ---------------- adjacency build: ONE atomic pass (padded rows) ----------------
__global__ void k_fillpad(const void* __restrict__ ei) {
    int e4 = blockIdx.x * blockDim.x + threadIdx.x;
    if (e4 >= N_EDGES / 4) return;
    int s0, s1, s2, s3, d0, d1, d2, d3;
    if (!g_is64) {
        const int4* ps = (const int4*)((const int*)ei);
        const int4* pd = (const int4*)((const int*)ei + N_EDGES);
        int4 vs = ps[e4]; int4 vd = pd[e4];
        s0 = vs.x; s1 = vs.y; s2 = vs.z; s3 = vs.w;
        d0 = vd.x; d1 = vd.y; d2 = vd.z; d3 = vd.w;
    } else {
        const long long* qs = (const long long*)ei + (long long)e4 * 4;
        const long long* qd = (const long long*)ei + N_EDGES + (long long)e4 * 4;
        s0 = (int)qs[0]; s1 = (int)qs[1]; s2 = (int)qs[2]; s3 = (int)qs[3];
        d0 = (int)qd[0]; d1 = (int)qd[1]; d2 = (int)qd[2]; d3 = (int)qd[3];
    }
#define FILL1(ss, dd) \
    if ((unsigned)(dd) < (unsigned)N_NODES && (unsigned)(ss) < (unsigned)N_NODES) { \
        int pos = atomicAdd(&g_deg[dd], 1); \
        if (pos < PAD) g_colpad[(dd) * PAD + pos] = (ss); \
    }
    FILL1(s0, d0) FILL1(s1, d1) FILL1(s2, d2) FILL1(s3, d3)
#undef FILL1
}

// ---------------- GEMM: z = x@Wl1^T, y = x@Wr1^T (packed f32x2) ----------------
// Tile: 128 nodes x 128 outs (outs 0..63 -> z, 64..127 -> y), K=64.
// 256 threads: tn = t/8 (4 nodes), tj = t%8 (16 outs as 8 f32x2 pairs).
#define WPAD2 132
#define APAD  132

__device__ __forceinline__ unsigned long long pack2(float v) {
    unsigned long long r;
    asm("mov.b64 %0, {%1, %1};" : "=l"(r) : "f"(v));
    return r;
}
__device__ __forceinline__ void fma2(unsigned long long& acc,
                                     unsigned long long a, unsigned long long w) {
    asm("fma.rn.f32x2 %0, %1, %2, %0;" : "+l"(acc) : "l"(a), "l"(w));
}
__device__ __forceinline__ void unpack2(unsigned long long v, float& lo, float& hi) {
    asm("mov.b64 {%0, %1}, %2;" : "=f"(lo), "=f"(hi) : "l"(v));
}

__global__ __launch_bounds__(256) void k_zy(
    const float* __restrict__ x,
    const float* __restrict__ Wl1, const float* __restrict__ Wr1)
{
    __shared__ __align__(16) float sWt[64][WPAD2];  // [k][j]: j<64 Wl1, j>=64 Wr1
    __shared__ __align__(16) float sAs[16][APAD];   // [k][node]

    int t = threadIdx.x;
    for (int i = t; i < 64 * 64; i += 256) {
        int j = i >> 6, k = i & 63;           // W[j][k] row-major
        sWt[k][j]      = Wl1[i];
        sWt[k][j + 64] = Wr1[i];
    }

    int tn = t >> 3;          // 0..31
    int tj = t & 7;           // 0..7
    int nodeBase = blockIdx.x * 128;

    unsigned long long acc[4][8];
#pragma unroll
    for (int i = 0; i < 4; i++)
#pragma unroll
        for (int jp = 0; jp < 8; jp++) acc[i][jp] = 0ull;

    int r  = t >> 1;              // staging row 0..127
    int kq = (t & 1) * 2;         // which 8 floats of the 16-chunk
    int nL = nodeBase + r; if (nL >= N_NODES) nL = N_NODES - 1;

    for (int ch = 0; ch < 4; ch++) {          // K=64 in 4 chunks of 16
        __syncthreads();
        {
            const float4* s4 = (const float4*)(x + (size_t)nL * 64 + ch * 16);
#pragma unroll
            for (int q = 0; q < 2; q++) {
                float4 v = s4[kq + q];
                int kk = (kq + q) * 4;
                sAs[kk][r] = v.x; sAs[kk + 1][r] = v.y;
                sAs[kk + 2][r] = v.z; sAs[kk + 3][r] = v.w;
            }
        }
        __syncthreads();
#pragma unroll
        for (int k = 0; k < 16; k++) {
            float4 a4 = *(const float4*)&sAs[k][tn * 4];
            unsigned long long a2[4];
            a2[0] = pack2(a4.x); a2[1] = pack2(a4.y);
            a2[2] = pack2(a4.z); a2[3] = pack2(a4.w);
            const float* wrow = &sWt[ch * 16 + k][tj * 16];
            unsigned long long w2[8];
#pragma unroll
            for (int c = 0; c < 4; c++) {
                float4 wv = *(const float4*)(wrow + c * 4);
                w2[c * 2]     = *(unsigned long long*)&wv.x;
                w2[c * 2 + 1] = *(unsigned long long*)&wv.z;
            }
#pragma unroll
            for (int i = 0; i < 4; i++)
#pragma unroll
                for (int jp = 0; jp < 8; jp++)
                    fma2(acc[i][jp], a2[i], w2[jp]);
        }
    }

    // store: outs tj*16..+15 contiguous; tj<4 -> z, tj>=4 -> y
#pragma unroll
    for (int i = 0; i < 4; i++) {
        int n = nodeBase + tn * 4 + i;
        if (n >= N_NODES) break;
        float* base = (tj < 4) ? (g_z + (size_t)n * 64 + tj * 16)
                               : (g_y + (size_t)n * 64 + (tj - 4) * 16);
        float4* dst = (float4*)base;
#pragma unroll
        for (int c = 0; c < 4; c++) {
            float lo0, hi0, lo1, hi1;
            unpack2(acc[i][c * 2],     lo0, hi0);
            unpack2(acc[i][c * 2 + 1], lo1, hi1);
            dst[c] = make_float4(lo0, hi0, lo1, hi1);
        }
    }
}

// ---------------- fused gather: h=relu(mean(z)+y+b1); p=h@Wl2^T; q=h@Wr2^T+b2 ----------------
// One warp per node. Half-warp per neighbor row (16 lanes x float4 = 64 floats).
__global__ void k_gather_fused(
    const float* __restrict__ b1,
    const float* __restrict__ Wl2, const float* __restrict__ Wr2,
    const float* __restrict__ b2)
{
    int w = (blockIdx.x * blockDim.x + threadIdx.x) >> 5;
    if (w >= N_NODES) return;
    int lane = threadIdx.x & 31;
    int q = lane & 15, half = lane >> 4;

    int deg = g_deg[w];
    int kd = min(deg, PAD);
    const float4* z4 = (const float4*)g_z;
    const int2* cp2 = (const int2*)g_colpad + w * (PAD / 2);

    float4 a0 = make_float4(0.f, 0.f, 0.f, 0.f);
    float4 a1 = make_float4(0.f, 0.f, 0.f, 0.f);
    int j = 0;
    for (; j + 4 <= kd; j += 4) {             // 4 edges per iter, 2 rows in flight/half
        int2 ca = cp2[j >> 1];
        int2 cb = cp2[(j >> 1) + 1];
        int c0 = half ? ca.y : ca.x;
        int c1 = half ? cb.y : cb.x;
        float4 v0 = z4[(size_t)c0 * 16 + q];
        float4 v1 = z4[(size_t)c1 * 16 + q];
        a0.x += v0.x; a0.y += v0.y; a0.z += v0.z; a0.w += v0.w;
        a1.x += v1.x; a1.y += v1.y; a1.z += v1.z; a1.w += v1.w;
    }
    for (; j < kd; j += 2) {                  // tail: up to 3 edges
        int2 ca = cp2[j >> 1];
        int c0 = half ? ca.y : ca.x;
        if (j + half < kd) {
            float4 v0 = z4[(size_t)c0 * 16 + q];
            a0.x += v0.x; a0.y += v0.y; a0.z += v0.z; a0.w += v0.w;
        }
    }
    a0.x += a1.x; a0.y += a1.y; a0.z += a1.z; a0.w += a1.w;
    // combine the two halves (same dims, disjoint edges)
    a0.x += __shfl_xor_sync(0xFFFFFFFFu, a0.x, 16);
    a0.y += __shfl_xor_sync(0xFFFFFFFFu, a0.y, 16);
    a0.z += __shfl_xor_sync(0xFFFFFFFFu, a0.z, 16);
    a0.w += __shfl_xor_sync(0xFFFFFFFFu, a0.w, 16);

    float inv = 1.f / (float)max(deg, 1);
    float4 yv = ((const float4*)g_y)[(size_t)w * 16 + q];
    float4 bb = ((const float4*)b1)[q];
    float h0 = fmaxf(a0.x * inv + yv.x + bb.x, 0.f);
    float h1 = fmaxf(a0.y * inv + yv.y + bb.y, 0.f);
    float h2 = fmaxf(a0.z * inv + yv.z + bb.z, 0.f);
    float h3 = fmaxf(a0.w * inv + yv.w + bb.w, 0.f);

    float4 l20 = ((const float4*)Wl2)[q];          // row 0
    float4 l21 = ((const float4*)(Wl2 + 64))[q];   // row 1
    float4 r20 = ((const float4*)Wr2)[q];
    float4 r21 = ((const float4*)(Wr2 + 64))[q];
    float p0 = h0 * l20.x + h1 * l20.y + h2 * l20.z + h3 * l20.w;
    float p1 = h0 * l21.x + h1 * l21.y + h2 * l21.z + h3 * l21.w;
    float q0 = h0 * r20.x + h1 * r20.y + h2 * r20.z + h3 * r20.w;
    float q1 = h0 * r21.x + h1 * r21.y + h2 * r21.z + h3 * r21.w;
#pragma unroll
    for (int o = 8; o > 0; o >>= 1) {
        p0 += __shfl_xor_sync(0xFFFFFFFFu, p0, o);
        p1 += __shfl_xor_sync(0xFFFFFFFFu, p1, o);
        q0 += __shfl_xor_sync(0xFFFFFFFFu, q0, o);
        q1 += __shfl_xor_sync(0xFFFFFFFFu, q1, o);
    }
    if (lane == 0) {
        g_p[w * 2]     = p0;
        g_p[w * 2 + 1] = p1;
        g_q[w * 2]     = q0 + b2[0];
        g_q[w * 2 + 1] = q1 + b2[1];
    }
}

// ---------------- layer 2: mean-aggregate p (2 floats/edge) + local q ----------------
__global__ void k_layer2_out(float* __restrict__ out) {
    int w = (blockIdx.x * blockDim.x + threadIdx.x) >> 5;
    if (w >= N_NODES) return;
    int lane = threadIdx.x & 31;
    int deg = g_deg[w];
    int kd = min(deg, PAD);
    const int* cp = g_colpad + w * PAD;
    float a0 = 0.f, a1 = 0.f;
    for (int j = lane; j < kd; j += 32) {
        int src = cp[j];
        float2 pv = *(const float2*)(g_p + src * 2);
        a0 += pv.x; a1 += pv.y;
    }
#pragma unroll
    for (int o = 16; o > 0; o >>= 1) {
        a0 += __shfl_xor_sync(0xFFFFFFFFu, a0, o);
        a1 += __shfl_xor_sync(0xFFFFFFFFu, a1, o);
    }
    if (lane == 0) {
        float inv = 1.f / (float)max(deg, 1);
        out[w * 2]     = a0 * inv + g_q[w * 2];
        out[w * 2 + 1] = a1 * inv + g_q[w * 2 + 1];
    }
}

// ---------------- launch ----------------
extern "C" void kernel_launch(void* const* d_in, const int* in_sizes, int n_in,
                              void* d_out, int out_size)
{
    const float* x   = (const float*)d_in[0];
    const void*  ei  = d_in[1];                 // int32 or int64, sniffed on device
    const float* Wl1 = (const float*)d_in[2];
    const float* Wr1 = (const float*)d_in[3];
    const float* b1  = (const float*)d_in[4];
    const float* Wl2 = (const float*)d_in[5];
    const float* Wr2 = (const float*)d_in[6];
    const float* b2  = (const float*)d_in[7];
    float* out = (float*)d_out;

    k_init<<<(N_NODES / 4 + 255) / 256, 256>>>((const int*)ei);
    k_fillpad<<<(N_EDGES / 4 + 255) / 256, 256>>>(ei);
    k_zy<<<(N_NODES + 127) / 128, 256>>>(x, Wl1, Wr1);
    int warps_grid = (N_NODES * 32 + 255) / 256;
    k_gather_fused<<<warps_grid, 256>>>(b1, Wl2, Wr2, b2);   // launch #4 -> profiled
    k_layer2_out<<<warps_grid, 256>>>(out);
}

// round 6
// speedup vs baseline: 1.3008x; 1.3008x over previous
#include <cuda_runtime.h>

#define N_NODES 100000
#define N_EDGES 1000000
#define PAD 64   // max stored degree; deg~Poisson(10), P(>64) ~ 0

// ---------------- device scratch (no allocations allowed) ----------------
__device__ int   g_is64;
__device__ int   g_deg[N_NODES];
__device__ int   g_colpad[N_NODES * PAD];
__device__ float g_z[N_NODES * 64];   // x @ Wl1^T
__device__ float g_y[N_NODES * 64];   // x @ Wr1^T
__device__ float g_p[N_NODES * 2];    // h @ Wl2^T  (to be mean-aggregated)
__device__ float g_q[N_NODES * 2];    // h @ Wr2^T + b2 (local term)

// ---------------- init: zero degrees + dtype sniff ----------------
__global__ void k_init(const int* __restrict__ ei32) {
    int i = blockIdx.x * blockDim.x + threadIdx.x;
    if (i < N_NODES / 4) ((int4*)g_deg)[i] = make_int4(0, 0, 0, 0);
    if (i == 0) {
        // int64 nonneg < 2^31 => every odd int32 word is 0
        int any = 0;
        for (int s = 1; s < 64; s += 2) any |= ei32[s];
        g_is64 = (any == 0) ? 1 : 0;
    }
}

// ---------------- adjacency build: ONE atomic pass (padded rows) ----------------
// processes edges [eBase, eBase + eCount) in groups of 4
__global__ void k_fillpad(const void* __restrict__ ei, int eBase4, int eCount4) {
    int e4 = blockIdx.x * blockDim.x + threadIdx.x;
    if (e4 >= eCount4) return;
    e4 += eBase4;
    int s0, s1, s2, s3, d0, d1, d2, d3;
    if (!g_is64) {
        const int4* ps = (const int4*)((const int*)ei);
        const int4* pd = (const int4*)((const int*)ei + N_EDGES);
        int4 vs = ps[e4]; int4 vd = pd[e4];
        s0 = vs.x; s1 = vs.y; s2 = vs.z; s3 = vs.w;
        d0 = vd.x; d1 = vd.y; d2 = vd.z; d3 = vd.w;
    } else {
        const long long* qs = (const long long*)ei + (long long)e4 * 4;
        const long long* qd = (const long long*)ei + N_EDGES + (long long)e4 * 4;
        s0 = (int)qs[0]; s1 = (int)qs[1]; s2 = (int)qs[2]; s3 = (int)qs[3];
        d0 = (int)qd[0]; d1 = (int)qd[1]; d2 = (int)qd[2]; d3 = (int)qd[3];
    }
#define FILL1(ss, dd) \
    if ((unsigned)(dd) < (unsigned)N_NODES && (unsigned)(ss) < (unsigned)N_NODES) { \
        int pos = atomicAdd(&g_deg[dd], 1); \
        if (pos < PAD) g_colpad[(dd) * PAD + pos] = (ss); \
    }
    FILL1(s0, d0) FILL1(s1, d1) FILL1(s2, d2) FILL1(s3, d3)
#undef FILL1
}

// ---------------- GEMM: out = x @ W^T, 128 nodes x 64 outs per block ----------------
// gridDim.y = 2: y=0 -> Wl1 -> g_z, y=1 -> Wr1 -> g_y.
// 256 threads: tn = t/8 (4 nodes each), tj = t%8 (8 outs as 4 f32x2 pairs).
#define WPAD 68
#define APAD 132

__device__ __forceinline__ unsigned long long pack2(float v) {
    unsigned long long r;
    asm("mov.b64 %0, {%1, %1};" : "=l"(r) : "f"(v));
    return r;
}
__device__ __forceinline__ void fma2(unsigned long long& acc,
                                     unsigned long long a, unsigned long long w) {
    asm("fma.rn.f32x2 %0, %1, %2, %0;" : "+l"(acc) : "l"(a), "l"(w));
}
__device__ __forceinline__ void unpack2(unsigned long long v, float& lo, float& hi) {
    asm("mov.b64 {%0, %1}, %2;" : "=f"(lo), "=f"(hi) : "l"(v));
}

__global__ __launch_bounds__(256) void k_zy(
    const float* __restrict__ x,
    const float* __restrict__ Wl1, const float* __restrict__ Wr1)
{
    __shared__ __align__(16) float sWt[64][WPAD];   // [k][j]
    __shared__ __align__(16) float sAs[16][APAD];   // [k][node]

    const float* W = (blockIdx.y == 0) ? Wl1 : Wr1;
    float* outg    = (blockIdx.y == 0) ? g_z : g_y;

    int t = threadIdx.x;
    for (int i = t; i < 64 * 64; i += 256) {
        int j = i >> 6, k = i & 63;           // W[j][k] row-major
        sWt[k][j] = W[i];
    }

    int tn = t >> 3;          // 0..31
    int tj = t & 7;           // 0..7
    int nodeBase = blockIdx.x * 128;

    unsigned long long acc[4][4];
#pragma unroll
    for (int i = 0; i < 4; i++)
#pragma unroll
        for (int jp = 0; jp < 4; jp++) acc[i][jp] = 0ull;

    int r  = t >> 1;              // staging row 0..127
    int kq = (t & 1) * 2;         // which 8 floats of the 16-chunk
    int nL = nodeBase + r; if (nL >= N_NODES) nL = N_NODES - 1;

    for (int ch = 0; ch < 4; ch++) {          // K=64 in 4 chunks of 16
        __syncthreads();
        {
            const float4* s4 = (const float4*)(x + (size_t)nL * 64 + ch * 16);
#pragma unroll
            for (int q = 0; q < 2; q++) {
                float4 v = s4[kq + q];
                int kk = (kq + q) * 4;
                sAs[kk][r] = v.x; sAs[kk + 1][r] = v.y;
                sAs[kk + 2][r] = v.z; sAs[kk + 3][r] = v.w;
            }
        }
        __syncthreads();
#pragma unroll
        for (int k = 0; k < 16; k++) {
            float4 a4 = *(const float4*)&sAs[k][tn * 4];
            unsigned long long a2[4];
            a2[0] = pack2(a4.x); a2[1] = pack2(a4.y);
            a2[2] = pack2(a4.z); a2[3] = pack2(a4.w);
            const float* wrow = &sWt[ch * 16 + k][tj * 8];
            unsigned long long w2[4];
            {
                float4 w0 = *(const float4*)(wrow);
                float4 w1 = *(const float4*)(wrow + 4);
                w2[0] = *(unsigned long long*)&w0.x;
                w2[1] = *(unsigned long long*)&w0.z;
                w2[2] = *(unsigned long long*)&w1.x;
                w2[3] = *(unsigned long long*)&w1.z;
            }
#pragma unroll
            for (int i = 0; i < 4; i++)
#pragma unroll
                for (int jp = 0; jp < 4; jp++)
                    fma2(acc[i][jp], a2[i], w2[jp]);
        }
    }

    // store: 8 contiguous outs at tj*8
#pragma unroll
    for (int i = 0; i < 4; i++) {
        int n = nodeBase + tn * 4 + i;
        if (n >= N_NODES) break;
        float4* dst = (float4*)(outg + (size_t)n * 64 + tj * 8);
#pragma unroll
        for (int c = 0; c < 2; c++) {
            float lo0, hi0, lo1, hi1;
            unpack2(acc[i][c * 2],     lo0, hi0);
            unpack2(acc[i][c * 2 + 1], lo1, hi1);
            dst[c] = make_float4(lo0, hi0, lo1, hi1);
        }
    }
}

// ---------------- fused gather: h=relu(mean(z)+y+b1); p=h@Wl2^T; q=h@Wr2^T+b2 ----------------
// One warp per node. Half-warp per neighbor row (16 lanes x float4 = 64 floats).
__global__ void k_gather_fused(
    const float* __restrict__ b1,
    const float* __restrict__ Wl2, const float* __restrict__ Wr2,
    const float* __restrict__ b2)
{
    int w = (blockIdx.x * blockDim.x + threadIdx.x) >> 5;
    if (w >= N_NODES) return;
    int lane = threadIdx.x & 31;
    int q = lane & 15, half = lane >> 4;

    int deg = g_deg[w];
    int kd = min(deg, PAD);
    const float4* z4 = (const float4*)g_z;
    const int2* cp2 = (const int2*)g_colpad + w * (PAD / 2);

    float4 a0 = make_float4(0.f, 0.f, 0.f, 0.f);
    float4 a1 = make_float4(0.f, 0.f, 0.f, 0.f);
    int j = 0;
    for (; j + 4 <= kd; j += 4) {             // 4 edges per iter, 2 rows in flight/half
        int2 ca = cp2[j >> 1];
        int2 cb = cp2[(j >> 1) + 1];
        int c0 = half ? ca.y : ca.x;
        int c1 = half ? cb.y : cb.x;
        float4 v0 = z4[(size_t)c0 * 16 + q];
        float4 v1 = z4[(size_t)c1 * 16 + q];
        a0.x += v0.x; a0.y += v0.y; a0.z += v0.z; a0.w += v0.w;
        a1.x += v1.x; a1.y += v1.y; a1.z += v1.z; a1.w += v1.w;
    }
    for (; j < kd; j += 2) {                  // tail: up to 3 edges
        int2 ca = cp2[j >> 1];
        int c0 = half ? ca.y : ca.x;
        if (j + half < kd) {
            float4 v0 = z4[(size_t)c0 * 16 + q];
            a0.x += v0.x; a0.y += v0.y; a0.z += v0.z; a0.w += v0.w;
        }
    }
    a0.x += a1.x; a0.y += a1.y; a0.z += a1.z; a0.w += a1.w;
    a0.x += __shfl_xor_sync(0xFFFFFFFFu, a0.x, 16);
    a0.y += __shfl_xor_sync(0xFFFFFFFFu, a0.y, 16);
    a0.z += __shfl_xor_sync(0xFFFFFFFFu, a0.z, 16);
    a0.w += __shfl_xor_sync(0xFFFFFFFFu, a0.w, 16);

    float inv = 1.f / (float)max(deg, 1);
    float4 yv = ((const float4*)g_y)[(size_t)w * 16 + q];
    float4 bb = ((const float4*)b1)[q];
    float h0 = fmaxf(a0.x * inv + yv.x + bb.x, 0.f);
    float h1 = fmaxf(a0.y * inv + yv.y + bb.y, 0.f);
    float h2 = fmaxf(a0.z * inv + yv.z + bb.z, 0.f);
    float h3 = fmaxf(a0.w * inv + yv.w + bb.w, 0.f);

    float4 l20 = ((const float4*)Wl2)[q];          // row 0
    float4 l21 = ((const float4*)(Wl2 + 64))[q];   // row 1
    float4 r20 = ((const float4*)Wr2)[q];
    float4 r21 = ((const float4*)(Wr2 + 64))[q];
    float p0 = h0 * l20.x + h1 * l20.y + h2 * l20.z + h3 * l20.w;
    float p1 = h0 * l21.x + h1 * l21.y + h2 * l21.z + h3 * l21.w;
    float q0 = h0 * r20.x + h1 * r20.y + h2 * r20.z + h3 * r20.w;
    float q1 = h0 * r21.x + h1 * r21.y + h2 * r21.z + h3 * r21.w;
#pragma unroll
    for (int o = 8; o > 0; o >>= 1) {
        p0 += __shfl_xor_sync(0xFFFFFFFFu, p0, o);
        p1 += __shfl_xor_sync(0xFFFFFFFFu, p1, o);
        q0 += __shfl_xor_sync(0xFFFFFFFFu, q0, o);
        q1 += __shfl_xor_sync(0xFFFFFFFFu, q1, o);
    }
    if (lane == 0) {
        g_p[w * 2]     = p0;
        g_p[w * 2 + 1] = p1;
        g_q[w * 2]     = q0 + b2[0];
        g_q[w * 2 + 1] = q1 + b2[1];
    }
}

// ---------------- layer 2: mean-aggregate p (2 floats/edge) + local q ----------------
__global__ void k_layer2_out(float* __restrict__ out) {
    int w = (blockIdx.x * blockDim.x + threadIdx.x) >> 5;
    if (w >= N_NODES) return;
    int lane = threadIdx.x & 31;
    int deg = g_deg[w];
    int kd = min(deg, PAD);
    const int* cp = g_colpad + w * PAD;
    float a0 = 0.f, a1 = 0.f;
    for (int j = lane; j < kd; j += 32) {
        int src = cp[j];
        float2 pv = *(const float2*)(g_p + src * 2);
        a0 += pv.x; a1 += pv.y;
    }
#pragma unroll
    for (int o = 16; o > 0; o >>= 1) {
        a0 += __shfl_xor_sync(0xFFFFFFFFu, a0, o);
        a1 += __shfl_xor_sync(0xFFFFFFFFu, a1, o);
    }
    if (lane == 0) {
        float inv = 1.f / (float)max(deg, 1);
        out[w * 2]     = a0 * inv + g_q[w * 2];
        out[w * 2 + 1] = a1 * inv + g_q[w * 2 + 1];
    }
}

// ---------------- launch ----------------
extern "C" void kernel_launch(void* const* d_in, const int* in_sizes, int n_in,
                              void* d_out, int out_size)
{
    const float* x   = (const float*)d_in[0];
    const void*  ei  = d_in[1];                 // int32 or int64, sniffed on device
    const float* Wl1 = (const float*)d_in[2];
    const float* Wr1 = (const float*)d_in[3];
    const float* b1  = (const float*)d_in[4];
    const float* Wl2 = (const float*)d_in[5];
    const float* Wr2 = (const float*)d_in[6];
    const float* b2  = (const float*)d_in[7];
    float* out = (float*)d_out;

    const int E4 = N_EDGES / 4;         // 250000
    const int HALF = E4 / 2;            // 125000

    k_init<<<(N_NODES / 4 + 255) / 256, 256>>>((const int*)ei);           // #1
    k_fillpad<<<(HALF + 255) / 256, 256>>>(ei, 0, HALF);                  // #2
    k_fillpad<<<(E4 - HALF + 255) / 256, 256>>>(ei, HALF, E4 - HALF);     // #3

    dim3 zyGrid((N_NODES + 127) / 128, 2);
    k_zy<<<zyGrid, 256>>>(x, Wl1, Wr1);                                   // #4 -> profiled

    int warps_grid = (N_NODES * 32 + 255) / 256;
    k_gather_fused<<<warps_grid, 256>>>(b1, Wl2, Wr2, b2);                // #5
    k_layer2_out<<<warps_grid, 256>>>(out);                               // #6
}

// round 7
// speedup vs baseline: 1.4398x; 1.1069x over previous
#include <cuda_runtime.h>

#define N_NODES 100000
#define N_EDGES 1000000
#define PAD 64   // max stored degree; deg~Poisson(10), P(>64) ~ 0

// ---------------- device scratch (no allocations allowed) ----------------
__device__ int   g_is64;
__device__ int   g_deg[N_NODES];
__device__ int   g_colpad[N_NODES * PAD];
__device__ float g_mean[N_NODES * 64];  // mean of neighbor x
__device__ float g_p[N_NODES * 2];      // h @ Wl2^T  (to be mean-aggregated)
__device__ float g_q[N_NODES * 2];      // h @ Wr2^T + b2 (local term)

// ---------------- init: zero degrees + dtype sniff ----------------
__global__ void k_init(const int* __restrict__ ei32) {
    int i = blockIdx.x * blockDim.x + threadIdx.x;
    if (i < N_NODES / 4) ((int4*)g_deg)[i] = make_int4(0, 0, 0, 0);
    if (i == 0) {
        // int64 nonneg < 2^31 => every odd int32 word is 0
        int any = 0;
        for (int s = 1; s < 64; s += 2) any |= ei32[s];
        g_is64 = (any == 0) ? 1 : 0;
    }
}

// ---------------- adjacency build: ONE atomic pass (padded rows) ----------------
__global__ void k_fillpad(const void* __restrict__ ei) {
    int e4 = blockIdx.x * blockDim.x + threadIdx.x;
    if (e4 >= N_EDGES / 4) return;
    int s0, s1, s2, s3, d0, d1, d2, d3;
    if (!g_is64) {
        const int4* ps = (const int4*)((const int*)ei);
        const int4* pd = (const int4*)((const int*)ei + N_EDGES);
        int4 vs = ps[e4]; int4 vd = pd[e4];
        s0 = vs.x; s1 = vs.y; s2 = vs.z; s3 = vs.w;
        d0 = vd.x; d1 = vd.y; d2 = vd.z; d3 = vd.w;
    } else {
        const long long* qs = (const long long*)ei + (long long)e4 * 4;
        const long long* qd = (const long long*)ei + N_EDGES + (long long)e4 * 4;
        s0 = (int)qs[0]; s1 = (int)qs[1]; s2 = (int)qs[2]; s3 = (int)qs[3];
        d0 = (int)qd[0]; d1 = (int)qd[1]; d2 = (int)qd[2]; d3 = (int)qd[3];
    }
#define FILL1(ss, dd) \
    if ((unsigned)(dd) < (unsigned)N_NODES && (unsigned)(ss) < (unsigned)N_NODES) { \
        int pos = atomicAdd(&g_deg[dd], 1); \
        if (pos < PAD) g_colpad[(dd) * PAD + pos] = (ss); \
    }
    FILL1(s0, d0) FILL1(s1, d1) FILL1(s2, d2) FILL1(s3, d3)
#undef FILL1
}

// ---------------- gather: mean of neighbor x (warp per node, float2 lanes) ----------------
__global__ void k_gather_mean(const float* __restrict__ x) {
    int w = (blockIdx.x * blockDim.x + threadIdx.x) >> 5;
    if (w >= N_NODES) return;
    int lane = threadIdx.x & 31;
    int deg = g_deg[w];
    int kd = min(deg, PAD);
    const int* cp = g_colpad + w * PAD;
    const float2* x2 = (const float2*)x;
    float ax0 = 0.f, ay0 = 0.f, ax1 = 0.f, ay1 = 0.f;
    float ax2 = 0.f, ay2 = 0.f, ax3 = 0.f, ay3 = 0.f;
    int j = 0;
    int nn = kd & ~3;
    for (; j < nn; j += 4) {
        int c0 = cp[j], c1 = cp[j + 1], c2 = cp[j + 2], c3 = cp[j + 3];
        float2 v0 = x2[c0 * 32 + lane];
        float2 v1 = x2[c1 * 32 + lane];
        float2 v2 = x2[c2 * 32 + lane];
        float2 v3 = x2[c3 * 32 + lane];
        ax0 += v0.x; ay0 += v0.y;
        ax1 += v1.x; ay1 += v1.y;
        ax2 += v2.x; ay2 += v2.y;
        ax3 += v3.x; ay3 += v3.y;
    }
    for (; j < kd; j++) {
        int c = cp[j];
        float2 v = x2[c * 32 + lane];
        ax0 += v.x; ay0 += v.y;
    }
    float inv = 1.f / (float)max(deg, 1);
    float2 r;
    r.x = ((ax0 + ax1) + (ax2 + ax3)) * inv;
    r.y = ((ay0 + ay1) + (ay2 + ay3)) * inv;
    ((float2*)g_mean)[w * 32 + lane] = r;
}

// ---------------- layer 1 GEMM (outer-product tiled, packed f32x2) ----------------
// h = relu([mean||x] @ [Wl1||Wr1]^T + b1);  p = h@Wl2^T;  q = h@Wr2^T + b2
#define KC 16
#define WPAD 68
#define APAD 132

__device__ __forceinline__ unsigned long long pack2(float v) {
    unsigned long long r;
    asm("mov.b64 %0, {%1, %1};" : "=l"(r) : "f"(v));
    return r;
}
__device__ __forceinline__ void fma2(unsigned long long& acc,
                                     unsigned long long a, unsigned long long w) {
    asm("fma.rn.f32x2 %0, %1, %2, %0;" : "+l"(acc) : "l"(a), "l"(w));
}
__device__ __forceinline__ void unpack2(unsigned long long v, float& lo, float& hi) {
    asm("mov.b64 {%0, %1}, %2;" : "=f"(lo), "=f"(hi) : "l"(v));
}

__global__ __launch_bounds__(256) void k_layer1(
    const float* __restrict__ x,
    const float* __restrict__ Wl1, const float* __restrict__ Wr1,
    const float* __restrict__ b1,
    const float* __restrict__ Wl2, const float* __restrict__ Wr2,
    const float* __restrict__ b2)
{
    __shared__ __align__(16) float sWt[128][WPAD];  // [k][j] transposed
    __shared__ __align__(16) float sAs[KC][APAD];   // [k][node] transposed chunk
    __shared__ float sL2[128], sR2[128], sB1[64];

    int t = threadIdx.x;
    for (int i = t; i < 64 * 64; i += 256) {
        int j = i >> 6, k = i & 63;
        sWt[k][j]      = Wl1[i];
        sWt[k + 64][j] = Wr1[i];
    }
    if (t < 128) { sL2[t] = Wl2[t]; sR2[t] = Wr2[t]; }
    if (t < 64)  sB1[t] = b1[t];

    int tn = t >> 3;          // 0..31 : node group (4 nodes)
    int tj = t & 7;           // 0..7  : out group (8 outs)
    int nodeBase = blockIdx.x * 128;

    unsigned long long acc[4][4];
#pragma unroll
    for (int i = 0; i < 4; i++)
#pragma unroll
        for (int jp = 0; jp < 4; jp++) acc[i][jp] = 0ull;

    int r  = t >> 1;              // staging row 0..127
    int kq = (t & 1) * 2;         // which 8 floats of the 16-chunk
    int nL = nodeBase + r; if (nL >= N_NODES) nL = N_NODES - 1;

    for (int ch = 0; ch < 8; ch++) {          // K=128: mean (0..3) then x (4..7)
        __syncthreads();
        {
            const float* src = (ch < 4) ? (g_mean + (size_t)nL * 64 + ch * 16)
                                        : (x      + (size_t)nL * 64 + (ch - 4) * 16);
            const float4* s4 = (const float4*)src;
#pragma unroll
            for (int q = 0; q < 2; q++) {
                float4 v = s4[kq + q];
                int kk = (kq + q) * 4;
                sAs[kk][r] = v.x; sAs[kk + 1][r] = v.y;
                sAs[kk + 2][r] = v.z; sAs[kk + 3][r] = v.w;
            }
        }
        __syncthreads();
        int kbase = ch * KC;
#pragma unroll
        for (int k = 0; k < KC; k++) {
            float4 a4 = *(const float4*)&sAs[k][tn * 4];
            unsigned long long a2[4];
            a2[0] = pack2(a4.x); a2[1] = pack2(a4.y);
            a2[2] = pack2(a4.z); a2[3] = pack2(a4.w);
            const float* wrow = &sWt[kbase + k][tj * 8];
            unsigned long long w2[4];
            {
                float4 w0 = *(const float4*)(wrow);
                float4 w1 = *(const float4*)(wrow + 4);
                w2[0] = *(unsigned long long*)&w0.x;
                w2[1] = *(unsigned long long*)&w0.z;
                w2[2] = *(unsigned long long*)&w1.x;
                w2[3] = *(unsigned long long*)&w1.z;
            }
#pragma unroll
            for (int i = 0; i < 4; i++)
#pragma unroll
                for (int jp = 0; jp < 4; jp++)
                    fma2(acc[i][jp], a2[i], w2[jp]);
        }
    }

    // epilogue: relu + bias, project to p (Wl2) and q (Wr2), reduce over tj lanes
    float bq0 = b2[0], bq1 = b2[1];
#pragma unroll
    for (int i = 0; i < 4; i++) {
        float p0 = 0.f, p1 = 0.f, q0 = 0.f, q1 = 0.f;
#pragma unroll
        for (int jp = 0; jp < 4; jp++) {
            float lo, hi;
            unpack2(acc[i][jp], lo, hi);
            int j = tj * 8 + jp * 2;
            float h0 = fmaxf(lo + sB1[j], 0.f);
            float h1 = fmaxf(hi + sB1[j + 1], 0.f);
            p0 += h0 * sL2[j]      + h1 * sL2[j + 1];
            p1 += h0 * sL2[64 + j] + h1 * sL2[64 + j + 1];
            q0 += h0 * sR2[j]      + h1 * sR2[j + 1];
            q1 += h0 * sR2[64 + j] + h1 * sR2[64 + j + 1];
        }
#pragma unroll
        for (int o = 4; o > 0; o >>= 1) {
            p0 += __shfl_xor_sync(0xFFFFFFFFu, p0, o);
            p1 += __shfl_xor_sync(0xFFFFFFFFu, p1, o);
            q0 += __shfl_xor_sync(0xFFFFFFFFu, q0, o);
            q1 += __shfl_xor_sync(0xFFFFFFFFu, q1, o);
        }
        if (tj == 0) {
            int n = nodeBase + tn * 4 + i;
            if (n < N_NODES) {
                g_p[n * 2]     = p0;
                g_p[n * 2 + 1] = p1;
                g_q[n * 2]     = q0 + bq0;
                g_q[n * 2 + 1] = q1 + bq1;
            }
        }
    }
}

// ---------------- layer 2: mean-aggregate p (2 floats/edge) + local q ----------------
__global__ void k_layer2_out(float* __restrict__ out) {
    int w = (blockIdx.x * blockDim.x + threadIdx.x) >> 5;
    if (w >= N_NODES) return;
    int lane = threadIdx.x & 31;
    int deg = g_deg[w];
    int kd = min(deg, PAD);
    const int* cp = g_colpad + w * PAD;
    float a0 = 0.f, a1 = 0.f;
    for (int j = lane; j < kd; j += 32) {
        int src = cp[j];
        float2 pv = *(const float2*)(g_p + src * 2);
        a0 += pv.x; a1 += pv.y;
    }
#pragma unroll
    for (int o = 16; o > 0; o >>= 1) {
        a0 += __shfl_xor_sync(0xFFFFFFFFu, a0, o);
        a1 += __shfl_xor_sync(0xFFFFFFFFu, a1, o);
    }
    if (lane == 0) {
        float inv = 1.f / (float)max(deg, 1);
        out[w * 2]     = a0 * inv + g_q[w * 2];
        out[w * 2 + 1] = a1 * inv + g_q[w * 2 + 1];
    }
}

// ---------------- launch ----------------
extern "C" void kernel_launch(void* const* d_in, const int* in_sizes, int n_in,
                              void* d_out, int out_size)
{
    const float* x   = (const float*)d_in[0];
    const void*  ei  = d_in[1];                 // int32 or int64, sniffed on device
    const float* Wl1 = (const float*)d_in[2];
    const float* Wr1 = (const float*)d_in[3];
    const float* b1  = (const float*)d_in[4];
    const float* Wl2 = (const float*)d_in[5];
    const float* Wr2 = (const float*)d_in[6];
    const float* b2  = (const float*)d_in[7];
    float* out = (float*)d_out;

    int warps_grid = (N_NODES * 32 + 255) / 256;

    k_init<<<(N_NODES / 4 + 255) / 256, 256>>>((const int*)ei);           // #1
    k_fillpad<<<(N_EDGES / 4 + 255) / 256, 256>>>(ei);                    // #2
    k_gather_mean<<<warps_grid, 256>>>(x);                                // #3
    k_layer1<<<(N_NODES + 127) / 128, 256>>>(x, Wl1, Wr1, b1,
                                             Wl2, Wr2, b2);               // #4 -> profiled
    k_layer2_out<<<warps_grid, 256>>>(out);                               // #5
}

// round 8
// speedup vs baseline: 1.9974x; 1.3873x over previous
#include <cuda_runtime.h>
#include <cstdint>

#define N_NODES 100000
#define N_EDGES 1000000
#define PAD 64   // max stored degree; deg~Poisson(10), P(>64) ~ 0

// ---------------- device scratch (no allocations allowed) ----------------
__device__ int   g_is64;
__device__ int   g_deg[N_NODES];
__device__ int   g_colpad[N_NODES * PAD];
__device__ float g_mean[N_NODES * 64];  // mean of neighbor x
__device__ float g_p[N_NODES * 2];      // h @ Wl2^T  (to be mean-aggregated)
__device__ float g_q[N_NODES * 2];      // h @ Wr2^T + b2 (local term)

// ---------------- init: zero degrees + dtype sniff ----------------
__global__ void k_init(const int* __restrict__ ei32) {
    int i = blockIdx.x * blockDim.x + threadIdx.x;
    if (i < N_NODES / 4) ((int4*)g_deg)[i] = make_int4(0, 0, 0, 0);
    if (i == 0) {
        // int64 nonneg < 2^31 => every odd int32 word is 0
        int any = 0;
        for (int s = 1; s < 64; s += 2) any |= ei32[s];
        g_is64 = (any == 0) ? 1 : 0;
    }
}

// ---------------- adjacency build: ONE atomic pass (padded rows) ----------------
__global__ void k_fillpad(const void* __restrict__ ei) {
    int e4 = blockIdx.x * blockDim.x + threadIdx.x;
    if (e4 >= N_EDGES / 4) return;
    int s0, s1, s2, s3, d0, d1, d2, d3;
    if (!g_is64) {
        const int4* ps = (const int4*)((const int*)ei);
        const int4* pd = (const int4*)((const int*)ei + N_EDGES);
        int4 vs = ps[e4]; int4 vd = pd[e4];
        s0 = vs.x; s1 = vs.y; s2 = vs.z; s3 = vs.w;
        d0 = vd.x; d1 = vd.y; d2 = vd.z; d3 = vd.w;
    } else {
        const long long* qs = (const long long*)ei + (long long)e4 * 4;
        const long long* qd = (const long long*)ei + N_EDGES + (long long)e4 * 4;
        s0 = (int)qs[0]; s1 = (int)qs[1]; s2 = (int)qs[2]; s3 = (int)qs[3];
        d0 = (int)qd[0]; d1 = (int)qd[1]; d2 = (int)qd[2]; d3 = (int)qd[3];
    }
#define FILL1(ss, dd) \
    if ((unsigned)(dd) < (unsigned)N_NODES && (unsigned)(ss) < (unsigned)N_NODES) { \
        int pos = atomicAdd(&g_deg[dd], 1); \
        if (pos < PAD) g_colpad[(dd) * PAD + pos] = (ss); \
    }
    FILL1(s0, d0) FILL1(s1, d1) FILL1(s2, d2) FILL1(s3, d3)
#undef FILL1
}

// ---------------- gather: mean of neighbor x (warp per node, float2 lanes) ----------------
__global__ void k_gather_mean(const float* __restrict__ x) {
    int w = (blockIdx.x * blockDim.x + threadIdx.x) >> 5;
    if (w >= N_NODES) return;
    int lane = threadIdx.x & 31;
    int deg = g_deg[w];
    int kd = min(deg, PAD);
    const int* cp = g_colpad + w * PAD;
    const float2* x2 = (const float2*)x;
    float ax0 = 0.f, ay0 = 0.f, ax1 = 0.f, ay1 = 0.f;
    float ax2 = 0.f, ay2 = 0.f, ax3 = 0.f, ay3 = 0.f;
    int j = 0;
    int nn = kd & ~3;
    for (; j < nn; j += 4) {
        int c0 = cp[j], c1 = cp[j + 1], c2 = cp[j + 2], c3 = cp[j + 3];
        float2 v0 = x2[c0 * 32 + lane];
        float2 v1 = x2[c1 * 32 + lane];
        float2 v2 = x2[c2 * 32 + lane];
        float2 v3 = x2[c3 * 32 + lane];
        ax0 += v0.x; ay0 += v0.y;
        ax1 += v1.x; ay1 += v1.y;
        ax2 += v2.x; ay2 += v2.y;
        ax3 += v3.x; ay3 += v3.y;
    }
    for (; j < kd; j++) {
        int c = cp[j];
        float2 v = x2[c * 32 + lane];
        ax0 += v.x; ay0 += v.y;
    }
    float inv = 1.f / (float)max(deg, 1);
    float2 r;
    r.x = ((ax0 + ax1) + (ax2 + ax3)) * inv;
    r.y = ((ay0 + ay1) + (ay2 + ay3)) * inv;
    ((float2*)g_mean)[w * 32 + lane] = r;
}

// ---------------- layer 1 GEMM on tensor cores (3xTF32 mma.sync) ----------------
// h = relu([mean||x] @ [Wl1||Wr1]^T + b1);  p = h@Wl2^T;  q = h@Wr2^T + b2
// Block: 256 thr / 8 warps. Tile: 128 nodes x 64 outs, K=128 in 4 chunks of 32.
// Warp w: nodes [w*16, w*16+16). Per warp: 8 n-tiles (m16n8k8), C = 8x4 f32 regs.
// Strides 36 (= 4 mod 32) make (4*row + k) bank-distinct for frag loads.
#define SAS 36
#define SWS 36

__device__ __forceinline__ uint32_t f2tf32(float v) {
    uint32_t r;
    asm("cvt.rna.tf32.f32 %0, %1;" : "=r"(r) : "f"(v));
    return r;
}
__device__ __forceinline__ void mma8(float* c,
    uint32_t a0, uint32_t a1, uint32_t a2, uint32_t a3,
    uint32_t b0, uint32_t b1)
{
    asm volatile(
        "mma.sync.aligned.m16n8k8.row.col.f32.tf32.tf32.f32 "
        "{%0,%1,%2,%3}, {%4,%5,%6,%7}, {%8,%9}, {%0,%1,%2,%3};"
        : "+f"(c[0]), "+f"(c[1]), "+f"(c[2]), "+f"(c[3])
        : "r"(a0), "r"(a1), "r"(a2), "r"(a3), "r"(b0), "r"(b1));
}

__global__ __launch_bounds__(256) void k_layer1_mma(
    const float* __restrict__ x,
    const float* __restrict__ Wl1, const float* __restrict__ Wr1,
    const float* __restrict__ b1,
    const float* __restrict__ Wl2, const float* __restrict__ Wr2,
    const float* __restrict__ b2)
{
    __shared__ __align__(16) float sA[128 * SAS];   // fp32 A chunk [node][k32]
    __shared__ float sWh[64 * SWS];                  // tf32-hi W chunk [j][k32]
    __shared__ float sWl[64 * SWS];                  // tf32-lo W chunk
    __shared__ float sL2[128], sR2[128], sB1[64];

    int t = threadIdx.x;
    int w = t >> 5, lane = t & 31;
    int g = lane >> 2, tq = lane & 3;
    int nodeBase = blockIdx.x * 128;

    if (t < 128) { sL2[t] = Wl2[t]; sR2[t] = Wr2[t]; }
    if (t < 64)  sB1[t] = b1[t];

    float c[8][4];
#pragma unroll
    for (int n = 0; n < 8; n++)
#pragma unroll
        for (int i = 0; i < 4; i++) c[n][i] = 0.f;

    // A staging mapping: thread -> node rr, half hf (16 floats)
    int rr = t >> 1, hf = t & 1;
    int nG = nodeBase + rr; if (nG >= N_NODES) nG = N_NODES - 1;

    for (int ch = 0; ch < 4; ch++) {      // K chunks: 0,1 = mean->Wl1; 2,3 = x->Wr1
        __syncthreads();
        // stage A chunk (128 x 32 fp32)
        {
            const float* srcRow = (ch < 2 ? g_mean : x) + (size_t)nG * 64 + (ch & 1) * 32 + hf * 16;
            const float4* s4 = (const float4*)srcRow;
            float4* d4 = (float4*)&sA[rr * SAS + hf * 16];
#pragma unroll
            for (int i = 0; i < 4; i++) d4[i] = s4[i];
        }
        // stage W chunk (64 x 32), pre-split into tf32 hi/lo
        {
            const float* Wsrc = (ch < 2) ? Wl1 : Wr1;
            int kofs = (ch & 1) * 32;
            for (int i = t; i < 64 * 32; i += 256) {
                int j = i >> 5, k = i & 31;
                float wv = Wsrc[j * 64 + kofs + k];
                uint32_t hb = f2tf32(wv);
                float hif = __uint_as_float(hb);
                uint32_t lb = f2tf32(wv - hif);
                sWh[j * SWS + k] = __uint_as_float(hb);
                sWl[j * SWS + k] = __uint_as_float(lb);
            }
        }
        __syncthreads();

#pragma unroll
        for (int ks = 0; ks < 4; ks++) {
            int k8 = ks * 8;
            const float* rA0 = &sA[(w * 16 + g) * SAS + k8];
            const float* rA1 = rA0 + 8 * SAS;
            float a0f = rA0[tq],     a1f = rA1[tq];
            float a2f = rA0[tq + 4], a3f = rA1[tq + 4];
            uint32_t ah0 = f2tf32(a0f), ah1 = f2tf32(a1f);
            uint32_t ah2 = f2tf32(a2f), ah3 = f2tf32(a3f);
            uint32_t al0 = f2tf32(a0f - __uint_as_float(ah0));
            uint32_t al1 = f2tf32(a1f - __uint_as_float(ah1));
            uint32_t al2 = f2tf32(a2f - __uint_as_float(ah2));
            uint32_t al3 = f2tf32(a3f - __uint_as_float(ah3));
#pragma unroll
            for (int n = 0; n < 8; n++) {
                int jw = (n * 8 + g) * SWS + k8;
                uint32_t bh0 = __float_as_uint(sWh[jw + tq]);
                uint32_t bh1 = __float_as_uint(sWh[jw + tq + 4]);
                uint32_t bl0 = __float_as_uint(sWl[jw + tq]);
                uint32_t bl1 = __float_as_uint(sWl[jw + tq + 4]);
                mma8(c[n], ah0, ah1, ah2, ah3, bh0, bh1);   // hi*hi
                mma8(c[n], al0, al1, al2, al3, bh0, bh1);   // lo*hi
                mma8(c[n], ah0, ah1, ah2, ah3, bl0, bl1);   // hi*lo
            }
        }
    }

    // epilogue: h = relu(C + b1), project to p (Wl2) / q (Wr2), quad-reduce
    float bq0 = b2[0], bq1 = b2[1];
    int r0 = nodeBase + w * 16 + g;
    int r1 = r0 + 8;
    float p00 = 0.f, p01 = 0.f, q00 = 0.f, q01 = 0.f;   // row r0
    float p10 = 0.f, p11 = 0.f, q10 = 0.f, q11 = 0.f;   // row r1
#pragma unroll
    for (int n = 0; n < 8; n++) {
        int j0 = n * 8 + 2 * tq, j1 = j0 + 1;
        float h00 = fmaxf(c[n][0] + sB1[j0], 0.f);
        float h01 = fmaxf(c[n][1] + sB1[j1], 0.f);
        float h10 = fmaxf(c[n][2] + sB1[j0], 0.f);
        float h11 = fmaxf(c[n][3] + sB1[j1], 0.f);
        p00 += h00 * sL2[j0]      + h01 * sL2[j1];
        p01 += h00 * sL2[64 + j0] + h01 * sL2[64 + j1];
        q00 += h00 * sR2[j0]      + h01 * sR2[j1];
        q01 += h00 * sR2[64 + j0] + h01 * sR2[64 + j1];
        p10 += h10 * sL2[j0]      + h11 * sL2[j1];
        p11 += h10 * sL2[64 + j0] + h11 * sL2[64 + j1];
        q10 += h10 * sR2[j0]      + h11 * sR2[j1];
        q11 += h10 * sR2[64 + j0] + h11 * sR2[64 + j1];
    }
#pragma unroll
    for (int o = 1; o <= 2; o <<= 1) {
        p00 += __shfl_xor_sync(0xFFFFFFFFu, p00, o);
        p01 += __shfl_xor_sync(0xFFFFFFFFu, p01, o);
        q00 += __shfl_xor_sync(0xFFFFFFFFu, q00, o);
        q01 += __shfl_xor_sync(0xFFFFFFFFu, q01, o);
        p10 += __shfl_xor_sync(0xFFFFFFFFu, p10, o);
        p11 += __shfl_xor_sync(0xFFFFFFFFu, p11, o);
        q10 += __shfl_xor_sync(0xFFFFFFFFu, q10, o);
        q11 += __shfl_xor_sync(0xFFFFFFFFu, q11, o);
    }
    if (tq == 0) {
        if (r0 < N_NODES) {
            g_p[r0 * 2]     = p00;
            g_p[r0 * 2 + 1] = p01;
            g_q[r0 * 2]     = q00 + bq0;
            g_q[r0 * 2 + 1] = q01 + bq1;
        }
        if (r1 < N_NODES) {
            g_p[r1 * 2]     = p10;
            g_p[r1 * 2 + 1] = p11;
            g_q[r1 * 2]     = q10 + bq0;
            g_q[r1 * 2 + 1] = q11 + bq1;
        }
    }
}

// ---------------- layer 2: mean-aggregate p (2 floats/edge) + local q ----------------
__global__ void k_layer2_out(float* __restrict__ out) {
    int w = (blockIdx.x * blockDim.x + threadIdx.x) >> 5;
    if (w >= N_NODES) return;
    int lane = threadIdx.x & 31;
    int deg = g_deg[w];
    int kd = min(deg, PAD);
    const int* cp = g_colpad + w * PAD;
    float a0 = 0.f, a1 = 0.f;
    for (int j = lane; j < kd; j += 32) {
        int src = cp[j];
        float2 pv = *(const float2*)(g_p + src * 2);
        a0 += pv.x; a1 += pv.y;
    }
#pragma unroll
    for (int o = 16; o > 0; o >>= 1) {
        a0 += __shfl_xor_sync(0xFFFFFFFFu, a0, o);
        a1 += __shfl_xor_sync(0xFFFFFFFFu, a1, o);
    }
    if (lane == 0) {
        float inv = 1.f / (float)max(deg, 1);
        out[w * 2]     = a0 * inv + g_q[w * 2];
        out[w * 2 + 1] = a1 * inv + g_q[w * 2 + 1];
    }
}

// ---------------- launch ----------------
extern "C" void kernel_launch(void* const* d_in, const int* in_sizes, int n_in,
                              void* d_out, int out_size)
{
    const float* x   = (const float*)d_in[0];
    const void*  ei  = d_in[1];                 // int32 or int64, sniffed on device
    const float* Wl1 = (const float*)d_in[2];
    const float* Wr1 = (const float*)d_in[3];
    const float* b1  = (const float*)d_in[4];
    const float* Wl2 = (const float*)d_in[5];
    const float* Wr2 = (const float*)d_in[6];
    const float* b2  = (const float*)d_in[7];
    float* out = (float*)d_out;

    int warps_grid = (N_NODES * 32 + 255) / 256;

    k_init<<<(N_NODES / 4 + 255) / 256, 256>>>((const int*)ei);           // #1
    k_fillpad<<<(N_EDGES / 4 + 255) / 256, 256>>>(ei);                    // #2
    k_gather_mean<<<warps_grid, 256>>>(x);                                // #3
    k_layer1_mma<<<(N_NODES + 127) / 128, 256>>>(x, Wl1, Wr1, b1,
                                                 Wl2, Wr2, b2);           // #4 -> profiled
    k_layer2_out<<<warps_grid, 256>>>(out);                               // #5
}

// round 9
// speedup vs baseline: 2.0760x; 1.0394x over previous
#include <cuda_runtime.h>
#include <cstdint>

#define N_NODES 100000
#define N_EDGES 1000000
#define PAD 64   // max stored degree; deg~Poisson(10), P(>64) ~ 0

// ---------------- device scratch (no allocations allowed) ----------------
__device__ int   g_is64;
__device__ int   g_deg[N_NODES];
__device__ int   g_colpad[N_NODES * PAD];
__device__ float g_mean[N_NODES * 64];  // mean of neighbor x
__device__ float g_p[N_NODES * 2];      // h @ Wl2^T  (to be mean-aggregated)
__device__ float g_q[N_NODES * 2];      // h @ Wr2^T + b2 (local term)
// pre-fragmented tf32 W (hi/lo), MMA-lane order: [K16][q][lane][c]
__device__ float g_WfH[16 * 4 * 32 * 4];
__device__ float g_WfL[16 * 4 * 32 * 4];

// ---------------- init: zero deg + dtype sniff + W fragment prep ----------------
__global__ void k_init(const int* __restrict__ ei32,
                       const float* __restrict__ Wl1,
                       const float* __restrict__ Wr1) {
    int i = blockIdx.x * blockDim.x + threadIdx.x;
    if (i < N_NODES / 4) ((int4*)g_deg)[i] = make_int4(0, 0, 0, 0);
    if (i == 0) {
        // int64 nonneg < 2^31 => every odd int32 word is 0
        int any = 0;
        for (int s = 1; s < 64; s += 2) any |= ei32[s];
        g_is64 = (any == 0) ? 1 : 0;
    }
    // W fragment prep: element i of the [K16][q][lane][c] layout
    if (i < 8192) {
        int K16 = i >> 9;
        int rem = i & 511;
        int q = rem >> 7;
        int lane = (rem >> 2) & 31;
        int c = rem & 3;
        int m = q * 4 + c;          // pair index 0..15
        int n = m >> 1;             // n-tile 0..7
        int r = m & 1;              // b-reg 0/1
        int g = lane >> 2, tq = lane & 3;
        int j = n * 8 + g;                       // output index 0..63
        int K = K16 * 8 + tq + r * 4;            // 0..127 in [Wl1||Wr1]
        float w = (K < 64) ? Wl1[j * 64 + K] : Wr1[j * 64 + K - 64];
        uint32_t hb;
        asm("cvt.rna.tf32.f32 %0, %1;" : "=r"(hb) : "f"(w));
        float hif = __uint_as_float(hb);
        uint32_t lb;
        float d = w - hif;
        asm("cvt.rna.tf32.f32 %0, %1;" : "=r"(lb) : "f"(d));
        g_WfH[i] = hif;
        g_WfL[i] = __uint_as_float(lb);
    }
}

// ---------------- adjacency build: ONE atomic pass (padded rows) ----------------
__global__ void k_fillpad(const void* __restrict__ ei) {
    int e4 = blockIdx.x * blockDim.x + threadIdx.x;
    if (e4 >= N_EDGES / 4) return;
    int s0, s1, s2, s3, d0, d1, d2, d3;
    if (!g_is64) {
        const int4* ps = (const int4*)((const int*)ei);
        const int4* pd = (const int4*)((const int*)ei + N_EDGES);
        int4 vs = ps[e4]; int4 vd = pd[e4];
        s0 = vs.x; s1 = vs.y; s2 = vs.z; s3 = vs.w;
        d0 = vd.x; d1 = vd.y; d2 = vd.z; d3 = vd.w;
    } else {
        const long long* qs = (const long long*)ei + (long long)e4 * 4;
        const long long* qd = (const long long*)ei + N_EDGES + (long long)e4 * 4;
        s0 = (int)qs[0]; s1 = (int)qs[1]; s2 = (int)qs[2]; s3 = (int)qs[3];
        d0 = (int)qd[0]; d1 = (int)qd[1]; d2 = (int)qd[2]; d3 = (int)qd[3];
    }
#define FILL1(ss, dd) \
    if ((unsigned)(dd) < (unsigned)N_NODES && (unsigned)(ss) < (unsigned)N_NODES) { \
        int pos = atomicAdd(&g_deg[dd], 1); \
        if (pos < PAD) g_colpad[(dd) * PAD + pos] = (ss); \
    }
    FILL1(s0, d0) FILL1(s1, d1) FILL1(s2, d2) FILL1(s3, d3)
#undef FILL1
}

// ---------------- gather: mean of neighbor x (warp per node, float2 lanes) ----------------
__global__ void k_gather_mean(const float* __restrict__ x) {
    int w = (blockIdx.x * blockDim.x + threadIdx.x) >> 5;
    if (w >= N_NODES) return;
    int lane = threadIdx.x & 31;
    int deg = g_deg[w];
    int kd = min(deg, PAD);
    const int* cp = g_colpad + w * PAD;
    const float2* x2 = (const float2*)x;
    float ax0 = 0.f, ay0 = 0.f, ax1 = 0.f, ay1 = 0.f;
    float ax2 = 0.f, ay2 = 0.f, ax3 = 0.f, ay3 = 0.f;
    int j = 0;
    int nn = kd & ~3;
    for (; j < nn; j += 4) {
        int c0 = cp[j], c1 = cp[j + 1], c2 = cp[j + 2], c3 = cp[j + 3];
        float2 v0 = x2[c0 * 32 + lane];
        float2 v1 = x2[c1 * 32 + lane];
        float2 v2 = x2[c2 * 32 + lane];
        float2 v3 = x2[c3 * 32 + lane];
        ax0 += v0.x; ay0 += v0.y;
        ax1 += v1.x; ay1 += v1.y;
        ax2 += v2.x; ay2 += v2.y;
        ax3 += v3.x; ay3 += v3.y;
    }
    for (; j < kd; j++) {
        int c = cp[j];
        float2 v = x2[c * 32 + lane];
        ax0 += v.x; ay0 += v.y;
    }
    float inv = 1.f / (float)max(deg, 1);
    float2 r;
    r.x = ((ax0 + ax1) + (ax2 + ax3)) * inv;
    r.y = ((ay0 + ay1) + (ay2 + ay3)) * inv;
    ((float2*)g_mean)[w * 32 + lane] = r;
}

// ---------------- layer 1 GEMM on tensor cores (3xTF32 mma.sync) ----------------
// h = relu([mean||x] @ [Wl1||Wr1]^T + b1);  p = h@Wl2^T;  q = h@Wr2^T + b2
// Block: 256 thr / 8 warps. Tile: 128 nodes x 64 outs, K=128 in 4 chunks of 32.
// W comes pre-fragmented (hi/lo) from g_WfH/g_WfL: one float4 = 2 n-tiles' b-regs.
#define SAS 36

__device__ __forceinline__ uint32_t f2tf32(float v) {
    uint32_t r;
    asm("cvt.rna.tf32.f32 %0, %1;" : "=r"(r) : "f"(v));
    return r;
}
__device__ __forceinline__ void mma8(float* c,
    uint32_t a0, uint32_t a1, uint32_t a2, uint32_t a3,
    uint32_t b0, uint32_t b1)
{
    asm volatile(
        "mma.sync.aligned.m16n8k8.row.col.f32.tf32.tf32.f32 "
        "{%0,%1,%2,%3}, {%4,%5,%6,%7}, {%8,%9}, {%0,%1,%2,%3};"
        : "+f"(c[0]), "+f"(c[1]), "+f"(c[2]), "+f"(c[3])
        : "r"(a0), "r"(a1), "r"(a2), "r"(a3), "r"(b0), "r"(b1));
}

__global__ __launch_bounds__(256) void k_layer1_mma(
    const float* __restrict__ x,
    const float* __restrict__ b1,
    const float* __restrict__ Wl2, const float* __restrict__ Wr2,
    const float* __restrict__ b2)
{
    __shared__ __align__(16) float sA[128 * SAS];   // fp32 A chunk [node][k32]
    __shared__ __align__(16) float sWH[2048];        // frag'd W hi, chunk = 4 ksteps
    __shared__ __align__(16) float sWL[2048];        // frag'd W lo
    __shared__ float sL2[128], sR2[128], sB1[64];

    int t = threadIdx.x;
    int w = t >> 5, lane = t & 31;
    int g = lane >> 2, tq = lane & 3;
    int nodeBase = blockIdx.x * 128;

    if (t < 128) { sL2[t] = Wl2[t]; sR2[t] = Wr2[t]; }
    if (t < 64)  sB1[t] = b1[t];

    float c[8][4];
#pragma unroll
    for (int n = 0; n < 8; n++)
#pragma unroll
        for (int i = 0; i < 4; i++) c[n][i] = 0.f;

    // A staging mapping: thread -> node rr, half hf (16 floats)
    int rr = t >> 1, hf = t & 1;
    int nG = nodeBase + rr; if (nG >= N_NODES) nG = N_NODES - 1;

    for (int ch = 0; ch < 4; ch++) {      // K chunks: 0,1 = mean->Wl1; 2,3 = x->Wr1
        __syncthreads();
        // stage A chunk (128 x 32 fp32)
        {
            const float* srcRow = (ch < 2 ? g_mean : x) + (size_t)nG * 64 + (ch & 1) * 32 + hf * 16;
            const float4* s4 = (const float4*)srcRow;
            float4* d4 = (float4*)&sA[rr * SAS + hf * 16];
#pragma unroll
            for (int i = 0; i < 4; i++) d4[i] = s4[i];
        }
        // stage pre-frag'd W chunk: 2048 floats each (pure copy, no cvt)
        {
            const float4* srcH = (const float4*)(g_WfH + ch * 2048);
            const float4* srcL = (const float4*)(g_WfL + ch * 2048);
            float4* dH = (float4*)sWH;
            float4* dL = (float4*)sWL;
#pragma unroll
            for (int i = 0; i < 2; i++) {
                dH[t + i * 256] = srcH[t + i * 256];
                dL[t + i * 256] = srcL[t + i * 256];
            }
        }
        __syncthreads();

#pragma unroll
        for (int ks = 0; ks < 4; ks++) {
            int k8 = ks * 8;
            const float* rA0 = &sA[(w * 16 + g) * SAS + k8];
            const float* rA1 = rA0 + 8 * SAS;
            float a0f = rA0[tq],     a1f = rA1[tq];
            float a2f = rA0[tq + 4], a3f = rA1[tq + 4];
            uint32_t ah0 = f2tf32(a0f), ah1 = f2tf32(a1f);
            uint32_t ah2 = f2tf32(a2f), ah3 = f2tf32(a3f);
            uint32_t al0 = f2tf32(a0f - __uint_as_float(ah0));
            uint32_t al1 = f2tf32(a1f - __uint_as_float(ah1));
            uint32_t al2 = f2tf32(a2f - __uint_as_float(ah2));
            uint32_t al3 = f2tf32(a3f - __uint_as_float(ah3));
#pragma unroll
            for (int q = 0; q < 4; q++) {
                // float4 = b-reg pairs for n-tiles (q*2, q*2+1)
                float4 vh = *(const float4*)&sWH[((ks * 4 + q) * 32 + lane) * 4];
                float4 vl = *(const float4*)&sWL[((ks * 4 + q) * 32 + lane) * 4];
                int n0 = q * 2, n1 = n0 + 1;
                uint32_t h0 = __float_as_uint(vh.x), h1 = __float_as_uint(vh.y);
                uint32_t h2 = __float_as_uint(vh.z), h3 = __float_as_uint(vh.w);
                uint32_t l0 = __float_as_uint(vl.x), l1 = __float_as_uint(vl.y);
                uint32_t l2 = __float_as_uint(vl.z), l3 = __float_as_uint(vl.w);
                mma8(c[n0], ah0, ah1, ah2, ah3, h0, h1);   // hi*hi
                mma8(c[n0], al0, al1, al2, al3, h0, h1);   // loA*hiB
                mma8(c[n0], ah0, ah1, ah2, ah3, l0, l1);   // hiA*loB
                mma8(c[n1], ah0, ah1, ah2, ah3, h2, h3);
                mma8(c[n1], al0, al1, al2, al3, h2, h3);
                mma8(c[n1], ah0, ah1, ah2, ah3, l2, l3);
            }
        }
    }

    // epilogue: h = relu(C + b1), project to p (Wl2) / q (Wr2), quad-reduce
    float bq0 = b2[0], bq1 = b2[1];
    int r0 = nodeBase + w * 16 + g;
    int r1 = r0 + 8;
    float p00 = 0.f, p01 = 0.f, q00 = 0.f, q01 = 0.f;   // row r0
    float p10 = 0.f, p11 = 0.f, q10 = 0.f, q11 = 0.f;   // row r1
#pragma unroll
    for (int n = 0; n < 8; n++) {
        int j0 = n * 8 + 2 * tq, j1 = j0 + 1;
        float h00 = fmaxf(c[n][0] + sB1[j0], 0.f);
        float h01 = fmaxf(c[n][1] + sB1[j1], 0.f);
        float h10 = fmaxf(c[n][2] + sB1[j0], 0.f);
        float h11 = fmaxf(c[n][3] + sB1[j1], 0.f);
        p00 += h00 * sL2[j0]      + h01 * sL2[j1];
        p01 += h00 * sL2[64 + j0] + h01 * sL2[64 + j1];
        q00 += h00 * sR2[j0]      + h01 * sR2[j1];
        q01 += h00 * sR2[64 + j0] + h01 * sR2[64 + j1];
        p10 += h10 * sL2[j0]      + h11 * sL2[j1];
        p11 += h10 * sL2[64 + j0] + h11 * sL2[64 + j1];
        q10 += h10 * sR2[j0]      + h11 * sR2[j1];
        q11 += h10 * sR2[64 + j0] + h11 * sR2[64 + j1];
    }
#pragma unroll
    for (int o = 1; o <= 2; o <<= 1) {
        p00 += __shfl_xor_sync(0xFFFFFFFFu, p00, o);
        p01 += __shfl_xor_sync(0xFFFFFFFFu, p01, o);
        q00 += __shfl_xor_sync(0xFFFFFFFFu, q00, o);
        q01 += __shfl_xor_sync(0xFFFFFFFFu, q01, o);
        p10 += __shfl_xor_sync(0xFFFFFFFFu, p10, o);
        p11 += __shfl_xor_sync(0xFFFFFFFFu, p11, o);
        q10 += __shfl_xor_sync(0xFFFFFFFFu, q10, o);
        q11 += __shfl_xor_sync(0xFFFFFFFFu, q11, o);
    }
    if (tq == 0) {
        if (r0 < N_NODES) {
            g_p[r0 * 2]     = p00;
            g_p[r0 * 2 + 1] = p01;
            g_q[r0 * 2]     = q00 + bq0;
            g_q[r0 * 2 + 1] = q01 + bq1;
        }
        if (r1 < N_NODES) {
            g_p[r1 * 2]     = p10;
            g_p[r1 * 2 + 1] = p11;
            g_q[r1 * 2]     = q10 + bq0;
            g_q[r1 * 2 + 1] = q11 + bq1;
        }
    }
}

// ---------------- layer 2: mean-aggregate p (2 floats/edge) + local q ----------------
__global__ void k_layer2_out(float* __restrict__ out) {
    int w = (blockIdx.x * blockDim.x + threadIdx.x) >> 5;
    if (w >= N_NODES) return;
    int lane = threadIdx.x & 31;
    int deg = g_deg[w];
    int kd = min(deg, PAD);
    const int* cp = g_colpad + w * PAD;
    float a0 = 0.f, a1 = 0.f;
    for (int j = lane; j < kd; j += 32) {
        int src = cp[j];
        float2 pv = *(const float2*)(g_p + src * 2);
        a0 += pv.x; a1 += pv.y;
    }
#pragma unroll
    for (int o = 16; o > 0; o >>= 1) {
        a0 += __shfl_xor_sync(0xFFFFFFFFu, a0, o);
        a1 += __shfl_xor_sync(0xFFFFFFFFu, a1, o);
    }
    if (lane == 0) {
        float inv = 1.f / (float)max(deg, 1);
        out[w * 2]     = a0 * inv + g_q[w * 2];
        out[w * 2 + 1] = a1 * inv + g_q[w * 2 + 1];
    }
}

// ---------------- launch ----------------
extern "C" void kernel_launch(void* const* d_in, const int* in_sizes, int n_in,
                              void* d_out, int out_size)
{
    const float* x   = (const float*)d_in[0];
    const void*  ei  = d_in[1];                 // int32 or int64, sniffed on device
    const float* Wl1 = (const float*)d_in[2];
    const float* Wr1 = (const float*)d_in[3];
    const float* b1  = (const float*)d_in[4];
    const float* Wl2 = (const float*)d_in[5];
    const float* Wr2 = (const float*)d_in[6];
    const float* b2  = (const float*)d_in[7];
    float* out = (float*)d_out;

    int warps_grid = (N_NODES * 32 + 255) / 256;

    k_init<<<(N_NODES / 4 + 255) / 256, 256>>>((const int*)ei, Wl1, Wr1);  // #1
    k_fillpad<<<(N_EDGES / 4 + 255) / 256, 256>>>(ei);                     // #2
    k_gather_mean<<<warps_grid, 256>>>(x);                                 // #3
    k_layer1_mma<<<(N_NODES + 127) / 128, 256>>>(x, b1, Wl2, Wr2, b2);     // #4 -> profiled
    k_layer2_out<<<warps_grid, 256>>>(out);                                // #5
}